// round 1
// baseline (speedup 1.0000x reference)
#include <cuda_runtime.h>
#include <cstdint>

typedef unsigned long long ull;

// Problem constants (fixed by the dataset)
constexpr int NN = 100000;
constexpr int EE = 1250000;
constexpr int DIN = 64;     // input dim of each layer (64 for both layers)
constexpr int KAGG = 512;   // 8 relations * 64
constexpr int NBLK = (NN + 1023) / 1024;  // 98 scan blocks

// ---------------- scratch (static device globals; no allocation) ------------
__device__ int g_deg[NN];
__device__ int g_rowptr[NN];
__device__ int g_cursor[NN];
__device__ int g_epack[EE];
__device__ int g_bsum[NBLK];
__device__ int g_bpre[NBLK];
__device__ float g_H[(size_t)NN * 64];       // layer-1 output (hidden)
__device__ float g_Agg[(size_t)NN * KAGG];   // normalized per-relation aggregates

// ---------------- f32x2 helpers --------------------------------------------
__device__ __forceinline__ void fma2(ull& d, ull a, ull b) {
    asm("fma.rn.f32x2 %0, %1, %2, %0;" : "+l"(d) : "l"(a), "l"(b));
}
__device__ __forceinline__ void unpk(float& x, float& y, ull v) {
    asm("mov.b64 {%0,%1}, %2;" : "=f"(x), "=f"(y) : "l"(v));
}

// ---------------- CSR build -------------------------------------------------
__global__ void k_zero_deg() {
    int i = blockIdx.x * blockDim.x + threadIdx.x;
    if (i < NN) g_deg[i] = 0;
}

__global__ void k_count(const int* __restrict__ dst) {
    int e = blockIdx.x * blockDim.x + threadIdx.x;
    if (e < EE) atomicAdd(&g_deg[dst[e]], 1);
}

__global__ void k_scan1() {
    int t = threadIdx.x;
    int i = blockIdx.x * 1024 + t;
    int lane = t & 31, wid = t >> 5;
    int orig = (i < NN) ? g_deg[i] : 0;
    int v = orig;
#pragma unroll
    for (int o = 1; o < 32; o <<= 1) {
        int nv = __shfl_up_sync(0xffffffffu, v, o);
        if (lane >= o) v += nv;
    }
    __shared__ int ws[32];
    if (lane == 31) ws[wid] = v;
    __syncthreads();
    if (wid == 0) {
        int wv = ws[lane];
#pragma unroll
        for (int o = 1; o < 32; o <<= 1) {
            int nv = __shfl_up_sync(0xffffffffu, wv, o);
            if (lane >= o) wv += nv;
        }
        ws[lane] = wv;
    }
    __syncthreads();
    int wpre = wid ? ws[wid - 1] : 0;
    if (i < NN) g_rowptr[i] = wpre + v - orig;
    if (t == 0) g_bsum[blockIdx.x] = ws[31];
}

__global__ void k_scan2() {
    __shared__ int s[128];
    int t = threadIdx.x;
    int v = (t < NBLK) ? g_bsum[t] : 0;
    s[t] = v;
    __syncthreads();
    for (int o = 1; o < 128; o <<= 1) {
        int add = (t >= o) ? s[t - o] : 0;
        __syncthreads();
        s[t] += add;
        __syncthreads();
    }
    if (t < NBLK) g_bpre[t] = (t == 0) ? 0 : s[t - 1];
}

__global__ void k_scan3() {
    int i = blockIdx.x * 1024 + threadIdx.x;
    if (i < NN) {
        int v = g_rowptr[i] + g_bpre[blockIdx.x];
        g_rowptr[i] = v;
        g_cursor[i] = v;
    }
}

__global__ void k_build(const int* __restrict__ src, const int* __restrict__ dst,
                        const int* __restrict__ et) {
    int e = blockIdx.x * blockDim.x + threadIdx.x;
    if (e < EE) {
        int d = dst[e];
        int p = atomicAdd(&g_cursor[d], 1);
        g_epack[p] = src[e] | (et[e] << 24);
    }
}

// ---------------- per-node relation aggregation -----------------------------
// one warp per dst node; per-relation sums in smem; lane r (<8) counts rel r
__global__ __launch_bounds__(256) void k_aggregate(const float* __restrict__ feat) {
    __shared__ float S[8][KAGG];
    int wid = threadIdx.x >> 5, lane = threadIdx.x & 31;
    int n = blockIdx.x * 8 + wid;
    if (n >= NN) return;
    float2* Sw = reinterpret_cast<float2*>(S[wid]);  // 256 float2 (8 rels x 32)
#pragma unroll
    for (int r = 0; r < 8; r++) Sw[r * 32 + lane] = make_float2(0.f, 0.f);

    int start = g_rowptr[n];
    int d = g_deg[n];
    int cnt = 0;
    const float2* fx = reinterpret_cast<const float2*>(feat);

    int pe = (d > 0) ? __ldg(g_epack + start) : 0;
    for (int i = 0; i < d; i++) {
        int cur = pe;
        if (i + 1 < d) pe = __ldg(g_epack + start + i + 1);
        int s = cur & 0xFFFFFF;
        int r = cur >> 24;
        if (lane == r) cnt++;
        float2 v = fx[(size_t)s * 32 + lane];
        float2 t = Sw[r * 32 + lane];
        t.x += v.x; t.y += v.y;
        Sw[r * 32 + lane] = t;
    }

    float inv = 1.0f / (float)max(cnt, 1);  // valid in lanes 0..7
    float2* Ao = reinterpret_cast<float2*>(g_Agg + (size_t)n * KAGG);
#pragma unroll
    for (int r = 0; r < 8; r++) {
        float fr = __shfl_sync(0xffffffffu, inv, r);
        float2 sv = Sw[r * 32 + lane];
        Ao[r * 32 + lane] = make_float2(sv.x * fr, sv.y * fr);
    }
}

// ---------------- GEMM: out = act(bias + X@Root + Agg@W) --------------------
// k-packed f32x2 accumulation: each ull acc holds (even-k partial, odd-k partial)
constexpr int BM = 128, BK = 16;

template <int DOUT, int TM, int CG>
__device__ __forceinline__ void gemm_seg(const float* __restrict__ Aseg, int lda,
                                         const float* __restrict__ Bseg, int Ksz,
                                         int m0, int tx, int ty,
                                         float (*As)[BK], float (*Bs)[BK + 4],
                                         ull (*acc)[4]) {
    int tid = ty * CG + tx;
    for (int k0 = 0; k0 < Ksz; k0 += BK) {
        // A tile: BM x BK, 2 float4 per thread, row-major (k contiguous)
#pragma unroll
        for (int p = 0; p < (BM * BK) / 1024; p++) {
            int idx = tid + p * 256;
            int m = idx >> 2;            // /(BK/4)
            int kq = idx & 3;
            int mg = m0 + m;
            float4 v = make_float4(0.f, 0.f, 0.f, 0.f);
            if (mg < NN)
                v = *reinterpret_cast<const float4*>(Aseg + (size_t)mg * lda + k0 + kq * 4);
            *reinterpret_cast<float4*>(&As[m][kq * 4]) = v;
        }
        // B tile: BK x DOUT -> transposed Bs[n][k]
        {
            constexpr int KP = 256 / DOUT;
            int n = tid % DOUT;
            int kq2 = tid / DOUT;
#pragma unroll
            for (int j = 0; j < BK / KP; j++) {
                int kk = kq2 + j * KP;
                Bs[n][kk] = Bseg[(size_t)(k0 + kk) * DOUT + n];
            }
        }
        __syncthreads();
#pragma unroll
        for (int kk = 0; kk < BK; kk += 4) {
            ull bu[4][2];
#pragma unroll
            for (int c = 0; c < 4; c++) {
                const ull* bp = reinterpret_cast<const ull*>(&Bs[tx * 4 + c][kk]);
                bu[c][0] = bp[0];
                bu[c][1] = bp[1];
            }
#pragma unroll
            for (int i = 0; i < TM; i++) {
                const ull* ap = reinterpret_cast<const ull*>(&As[ty * TM + i][kk]);
                ull a0 = ap[0], a1 = ap[1];
#pragma unroll
                for (int c = 0; c < 4; c++) {
                    fma2(acc[i][c], a0, bu[c][0]);
                    fma2(acc[i][c], a1, bu[c][1]);
                }
            }
        }
        __syncthreads();
    }
}

template <int DOUT, bool RELU>
__global__ __launch_bounds__(256, 2) void k_gemm(const float* __restrict__ X,
                                                 const float* __restrict__ Root,
                                                 const float* __restrict__ Agg,
                                                 const float* __restrict__ W,
                                                 const float* __restrict__ bias,
                                                 float* __restrict__ out) {
    constexpr int CG = DOUT / 4;       // column groups (4 cols each)
    constexpr int RG = 256 / CG;       // row groups
    constexpr int TM = BM / RG;        // rows per thread
    __shared__ __align__(16) float As[BM][BK];
    __shared__ __align__(16) float Bs[DOUT][BK + 4];
    int tid = threadIdx.x;
    int tx = tid % CG, ty = tid / CG;
    int m0 = blockIdx.x * BM;

    ull acc[TM][4];
#pragma unroll
    for (int i = 0; i < TM; i++)
#pragma unroll
        for (int c = 0; c < 4; c++) acc[i][c] = 0ull;

    gemm_seg<DOUT, TM, CG>(X, DIN, Root, DIN, m0, tx, ty, As, Bs, acc);
    gemm_seg<DOUT, TM, CG>(Agg, KAGG, W, KAGG, m0, tx, ty, As, Bs, acc);

    float4 bv = *reinterpret_cast<const float4*>(&bias[tx * 4]);
    const float bb[4] = {bv.x, bv.y, bv.z, bv.w};
#pragma unroll
    for (int i = 0; i < TM; i++) {
        int mg = m0 + ty * TM + i;
        if (mg < NN) {
            float o[4];
#pragma unroll
            for (int c = 0; c < 4; c++) {
                float lo, hi;
                unpk(lo, hi, acc[i][c]);
                float v = lo + hi + bb[c];
                if (RELU) v = fmaxf(v, 0.f);
                o[c] = v;
            }
            *reinterpret_cast<float4*>(&out[(size_t)mg * DOUT + tx * 4]) =
                make_float4(o[0], o[1], o[2], o[3]);
        }
    }
}

// ---------------- launch ----------------------------------------------------
extern "C" void kernel_launch(void* const* d_in, const int* in_sizes, int n_in,
                              void* d_out, int out_size) {
    const float* x     = (const float*)d_in[0];
    const float* W1    = (const float*)d_in[1];
    const float* root1 = (const float*)d_in[2];
    const float* b1    = (const float*)d_in[3];
    const float* W2    = (const float*)d_in[4];
    const float* root2 = (const float*)d_in[5];
    const float* b2    = (const float*)d_in[6];
    const int*   src   = (const int*)d_in[7];
    const int*   dst   = (const int*)d_in[8];
    const int*   et    = (const int*)d_in[9];
    float* out = (float*)d_out;

    float* H;
    float* Agg;
    cudaGetSymbolAddress((void**)&H, g_H);
    cudaGetSymbolAddress((void**)&Agg, g_Agg);

    const int egrid = (EE + 255) / 256;
    const int ngrid = NBLK;  // 98 blocks of 1024 covers NN
    const int agrid = (NN + 7) / 8;
    const int ggrid = (NN + BM - 1) / BM;

    // CSR build (shared by both layers)
    k_zero_deg<<<ngrid, 1024>>>();
    k_count<<<egrid, 256>>>(dst);
    k_scan1<<<ngrid, 1024>>>();
    k_scan2<<<1, 128>>>();
    k_scan3<<<ngrid, 1024>>>();
    k_build<<<egrid, 256>>>(src, dst, et);

    // Layer 1
    k_aggregate<<<agrid, 256>>>(x);
    k_gemm<64, true><<<ggrid, 256>>>(x, root1, Agg, W1, b1, H);

    // Layer 2
    k_aggregate<<<agrid, 256>>>(H);
    k_gemm<32, false><<<ggrid, 256>>>(H, root2, Agg, W2, b2, out);
}

// round 2
// speedup vs baseline: 1.7353x; 1.7353x over previous
#include <cuda_runtime.h>
#include <cstdint>

typedef unsigned long long ull;

// Problem constants (fixed by the dataset)
constexpr int NN = 100000;
constexpr int EE = 1250000;
constexpr int DIN = 64;     // input dim of each layer
constexpr int KAGG = 512;   // 8 relations * 64
constexpr int NBLK = (NN + 1023) / 1024;  // 98 scan blocks

// ---------------- scratch (static device globals; no allocation) ------------
__device__ int g_deg[NN];
__device__ int g_rowptr[NN];
__device__ int g_cursor[NN];
__device__ int g_epack[EE];
__device__ int g_bsum[NBLK];
__device__ int g_bpre[NBLK];
__device__ float g_H[(size_t)NN * 64];       // layer-1 output (hidden)
__device__ float g_Agg[(size_t)NN * KAGG];   // normalized per-relation aggregates

// ---------------- f32x2 helpers --------------------------------------------
__device__ __forceinline__ void fma2(ull& d, ull a, ull b) {
    asm("fma.rn.f32x2 %0, %1, %2, %0;" : "+l"(d) : "l"(a), "l"(b));
}
__device__ __forceinline__ void unpk(float& x, float& y, ull v) {
    asm("mov.b64 {%0,%1}, %2;" : "=f"(x), "=f"(y) : "l"(v));
}
__device__ __forceinline__ ull pk2(float x, float y) {
    ull u;
    asm("mov.b64 %0, {%1,%2};" : "=l"(u) : "f"(x), "f"(y));
    return u;
}

// ---------------- CSR build -------------------------------------------------
__global__ void k_count(const int* __restrict__ dst) {
    int e = blockIdx.x * blockDim.x + threadIdx.x;
    if (e < EE) atomicAdd(&g_deg[dst[e]], 1);
}

__global__ void k_scan1() {
    int t = threadIdx.x;
    int i = blockIdx.x * 1024 + t;
    int lane = t & 31, wid = t >> 5;
    int orig = (i < NN) ? g_deg[i] : 0;
    int v = orig;
#pragma unroll
    for (int o = 1; o < 32; o <<= 1) {
        int nv = __shfl_up_sync(0xffffffffu, v, o);
        if (lane >= o) v += nv;
    }
    __shared__ int ws[32];
    if (lane == 31) ws[wid] = v;
    __syncthreads();
    if (wid == 0) {
        int wv = ws[lane];
#pragma unroll
        for (int o = 1; o < 32; o <<= 1) {
            int nv = __shfl_up_sync(0xffffffffu, wv, o);
            if (lane >= o) wv += nv;
        }
        ws[lane] = wv;
    }
    __syncthreads();
    int wpre = wid ? ws[wid - 1] : 0;
    if (i < NN) g_rowptr[i] = wpre + v - orig;
    if (t == 0) g_bsum[blockIdx.x] = ws[31];
}

__global__ void k_scan2() {
    __shared__ int s[128];
    int t = threadIdx.x;
    int v = (t < NBLK) ? g_bsum[t] : 0;
    s[t] = v;
    __syncthreads();
    for (int o = 1; o < 128; o <<= 1) {
        int add = (t >= o) ? s[t - o] : 0;
        __syncthreads();
        s[t] += add;
        __syncthreads();
    }
    if (t < NBLK) g_bpre[t] = (t == 0) ? 0 : s[t - 1];
}

__global__ void k_scan3() {
    int i = blockIdx.x * 1024 + threadIdx.x;
    if (i < NN) {
        int v = g_rowptr[i] + g_bpre[blockIdx.x];
        g_rowptr[i] = v;
        g_cursor[i] = v;
    }
}

__global__ void k_build(const int* __restrict__ src, const int* __restrict__ dst,
                        const int* __restrict__ et) {
    int e = blockIdx.x * blockDim.x + threadIdx.x;
    if (e < EE) {
        int d = dst[e];
        int p = atomicAdd(&g_cursor[d], 1);
        g_epack[p] = src[e] | (et[e] << 24);
    }
}

// ---------------- per-node relation aggregation -----------------------------
// one warp per dst node; per-relation sums in smem; lane r (<8) counts rel r
__global__ __launch_bounds__(256) void k_aggregate(const float* __restrict__ feat) {
    __shared__ float S[8][KAGG];
    int wid = threadIdx.x >> 5, lane = threadIdx.x & 31;
    int n = blockIdx.x * 8 + wid;
    if (n >= NN) return;
    float2* Sw = reinterpret_cast<float2*>(S[wid]);  // 256 float2 (8 rels x 32)
#pragma unroll
    for (int r = 0; r < 8; r++) Sw[r * 32 + lane] = make_float2(0.f, 0.f);

    int start = g_rowptr[n];
    int d = g_deg[n];
    int cnt = 0;
    const float2* fx = reinterpret_cast<const float2*>(feat);

    int pe = (d > 0) ? __ldg(g_epack + start) : 0;
    for (int i = 0; i < d; i++) {
        int cur = pe;
        if (i + 1 < d) pe = __ldg(g_epack + start + i + 1);
        int s = cur & 0xFFFFFF;
        int r = cur >> 24;
        if (lane == r) cnt++;
        float2 v = fx[(size_t)s * 32 + lane];
        float2 t = Sw[r * 32 + lane];
        t.x += v.x; t.y += v.y;
        Sw[r * 32 + lane] = t;
    }

    float inv = 1.0f / (float)max(cnt, 1);  // valid in lanes 0..7
    float2* Ao = reinterpret_cast<float2*>(g_Agg + (size_t)n * KAGG);
#pragma unroll
    for (int r = 0; r < 8; r++) {
        float fr = __shfl_sync(0xffffffffu, inv, r);
        float2 sv = Sw[r * 32 + lane];
        Ao[r * 32 + lane] = make_float2(sv.x * fr, sv.y * fr);
    }
}

// ---------------- GEMM: out = act(bias + X@Root + Agg@W) --------------------
// Virtual K = 576 (64 root + 512 relation). k-packed f32x2 accumulation:
// each ull acc holds (even-k partial, odd-k partial) for one output column.
// Conflict-free smem: B pre-packed as ull[BK/2][DOUT] with strided column
// assignment (n = tx + CG*c); A padded to stride BK+2 (=18 words).
constexpr int BM = 128, BK = 16;
constexpr int NTILE = (DIN + KAGG) / BK;  // 36

template <int DOUT, bool RELU>
__global__ __launch_bounds__(256, 2) void k_gemm(const float* __restrict__ X,
                                                 const float* __restrict__ Root,
                                                 const float* __restrict__ Agg,
                                                 const float* __restrict__ W,
                                                 const float* __restrict__ bias,
                                                 float* __restrict__ out) {
    constexpr int CG = DOUT / 4;       // threads along n (4 strided cols each)
    constexpr int RG = 256 / CG;       // threads along m
    constexpr int TM = BM / RG;        // rows per thread
    constexpr int NB = (8 * DOUT) / 256;  // b k-pairs per thread (2 or 1)

    __shared__ float As[BM][BK + 2];
    __shared__ ull Bs[BK / 2][DOUT];

    int tid = threadIdx.x;
    int tx = tid % CG, ty = tid / CG;
    int m0 = blockIdx.x * BM;

    ull acc[TM][4];
#pragma unroll
    for (int i = 0; i < TM; i++)
#pragma unroll
        for (int c = 0; c < 4; c++) acc[i][c] = 0ull;

    float4 av[2];
    float b0[NB], b1[NB];

    auto ldtile = [&](int t) {
        const float* Aseg;
        const float* Bseg;
        int lda, koff;
        if (t < DIN / BK) { Aseg = X; Bseg = Root; lda = DIN; koff = t * BK; }
        else { Aseg = Agg; Bseg = W; lda = KAGG; koff = (t - DIN / BK) * BK; }
#pragma unroll
        for (int p = 0; p < 2; p++) {
            int idx = tid + p * 256;
            int m = idx >> 2, kq = idx & 3;
            int mg = m0 + m;
            av[p] = (mg < NN)
                ? *reinterpret_cast<const float4*>(Aseg + (size_t)mg * lda + koff + kq * 4)
                : make_float4(0.f, 0.f, 0.f, 0.f);
        }
#pragma unroll
        for (int p = 0; p < NB; p++) {
            int pid = tid + p * 256;
            int n = pid % DOUT, kp = pid / DOUT;
            b0[p] = Bseg[(size_t)(koff + 2 * kp) * DOUT + n];
            b1[p] = Bseg[(size_t)(koff + 2 * kp + 1) * DOUT + n];
        }
    };

    auto sttile = [&]() {
#pragma unroll
        for (int p = 0; p < 2; p++) {
            int idx = tid + p * 256;
            int m = idx >> 2, kq = idx & 3;
            // two STS.64 (row stride 18 floats keeps 8B alignment, not 16B)
            float2* dstp = reinterpret_cast<float2*>(&As[m][kq * 4]);
            dstp[0] = make_float2(av[p].x, av[p].y);
            dstp[1] = make_float2(av[p].z, av[p].w);
        }
#pragma unroll
        for (int p = 0; p < NB; p++) {
            int pid = tid + p * 256;
            int n = pid % DOUT, kp = pid / DOUT;
            Bs[kp][n] = pk2(b0[p], b1[p]);
        }
    };

    ldtile(0);
    for (int t = 0; t < NTILE; t++) {
        sttile();
        __syncthreads();
        if (t + 1 < NTILE) ldtile(t + 1);
#pragma unroll
        for (int kp = 0; kp < BK / 2; kp++) {
            ull bu[4];
#pragma unroll
            for (int c = 0; c < 4; c++) bu[c] = Bs[kp][tx + CG * c];
#pragma unroll
            for (int i = 0; i < TM; i++) {
                ull a = *reinterpret_cast<const ull*>(&As[ty * TM + i][kp * 2]);
#pragma unroll
                for (int c = 0; c < 4; c++) fma2(acc[i][c], a, bu[c]);
            }
        }
        __syncthreads();
    }

#pragma unroll
    for (int i = 0; i < TM; i++) {
        int mg = m0 + ty * TM + i;
        if (mg < NN) {
#pragma unroll
            for (int c = 0; c < 4; c++) {
                int n = tx + CG * c;
                float lo, hi;
                unpk(lo, hi, acc[i][c]);
                float v = lo + hi + __ldg(bias + n);
                if (RELU) v = fmaxf(v, 0.f);
                out[(size_t)mg * DOUT + n] = v;
            }
        }
    }
}

// ---------------- launch ----------------------------------------------------
extern "C" void kernel_launch(void* const* d_in, const int* in_sizes, int n_in,
                              void* d_out, int out_size) {
    const float* x     = (const float*)d_in[0];
    const float* W1    = (const float*)d_in[1];
    const float* root1 = (const float*)d_in[2];
    const float* b1    = (const float*)d_in[3];
    const float* W2    = (const float*)d_in[4];
    const float* root2 = (const float*)d_in[5];
    const float* b2    = (const float*)d_in[6];
    const int*   src   = (const int*)d_in[7];
    const int*   dst   = (const int*)d_in[8];
    const int*   et    = (const int*)d_in[9];
    float* out = (float*)d_out;

    float* H;
    float* Agg;
    int* degp;
    cudaGetSymbolAddress((void**)&H, g_H);
    cudaGetSymbolAddress((void**)&Agg, g_Agg);
    cudaGetSymbolAddress((void**)&degp, g_deg);

    const int egrid = (EE + 255) / 256;
    const int ngrid = NBLK;
    const int agrid = (NN + 7) / 8;
    const int ggrid = (NN + BM - 1) / BM;

    // CSR build (shared by both layers)
    cudaMemsetAsync(degp, 0, NN * sizeof(int));
    k_count<<<egrid, 256>>>(dst);
    k_scan1<<<ngrid, 1024>>>();
    k_scan2<<<1, 128>>>();
    k_scan3<<<ngrid, 1024>>>();
    k_build<<<egrid, 256>>>(src, dst, et);

    // Layer 1
    k_aggregate<<<agrid, 256>>>(x);
    k_gemm<64, true><<<ggrid, 256>>>(x, root1, Agg, W1, b1, H);

    // Layer 2
    k_aggregate<<<agrid, 256>>>(H);
    k_gemm<32, false><<<ggrid, 256>>>(H, root2, Agg, W2, b2, out);
}

// round 4
// speedup vs baseline: 1.9573x; 1.1279x over previous
#include <cuda_runtime.h>
#include <cuda_bf16.h>
#include <cstdint>

typedef unsigned long long ull;

// Problem constants
constexpr int NN = 100000;
constexpr int EE = 1250000;
constexpr int KAGG = 512;                 // 8 rels * 64
constexpr int KTOT = 576;                 // 64 (root) + 512
constexpr int NBLK = (NN + 1023) / 1024;  // 98
constexpr int KC = 64;                    // k per chunk
constexpr int NCH = KTOT / KC;            // 9
constexpr int AS = 72;                    // smem row stride in bf16 (144 B)

// ---------------- scratch ---------------------------------------------------
__device__ int g_deg[NN];
__device__ int g_rowptr[NN];
__device__ int g_cursor[NN];
__device__ int g_epack[EE];
__device__ int g_bsum[NBLK];
__device__ int g_bpre[NBLK];
__device__ float g_H[(size_t)NN * 64];
__device__ float g_Agg[(size_t)NN * KAGG];
__device__ __nv_bfloat16 g_Wt1h[64 * KTOT];
__device__ __nv_bfloat16 g_Wt1l[64 * KTOT];
__device__ __nv_bfloat16 g_Wt2h[32 * KTOT];
__device__ __nv_bfloat16 g_Wt2l[32 * KTOT];

// ---------------- helpers ---------------------------------------------------
__device__ __forceinline__ uint32_t smem_u32(const void* p) {
    uint32_t a;
    asm("{ .reg .u64 t; cvta.to.shared.u64 t, %1; cvt.u32.u64 %0, t; }" : "=r"(a) : "l"(p));
    return a;
}
__device__ __forceinline__ void sts128(uint32_t a, uint32_t x, uint32_t y, uint32_t z, uint32_t w) {
    asm volatile("st.shared.v4.b32 [%0], {%1,%2,%3,%4};" :: "r"(a), "r"(x), "r"(y), "r"(z), "r"(w) : "memory");
}
__device__ __forceinline__ uint32_t lds32(uint32_t a) {
    uint32_t v;
    asm volatile("ld.shared.b32 %0, [%1];" : "=r"(v) : "r"(a));
    return v;
}
__device__ __forceinline__ uint32_t cvt2(float lo, float hi) {
    uint32_t r;
    asm("cvt.rn.satfinite.bf16x2.f32 %0, %1, %2;" : "=r"(r) : "f"(hi), "f"(lo));
    return r;
}
__device__ __forceinline__ void ldmx4(uint32_t* r, uint32_t a) {
    asm volatile("ldmatrix.sync.aligned.m8n8.x4.shared.b16 {%0,%1,%2,%3}, [%4];"
                 : "=r"(r[0]), "=r"(r[1]), "=r"(r[2]), "=r"(r[3]) : "r"(a));
}
__device__ __forceinline__ void mma16816(float* c, const uint32_t* a, uint32_t b0, uint32_t b1) {
    asm volatile("mma.sync.aligned.m16n8k16.row.col.f32.bf16.bf16.f32 "
                 "{%0,%1,%2,%3}, {%4,%5,%6,%7}, {%8,%9}, {%0,%1,%2,%3};"
                 : "+f"(c[0]), "+f"(c[1]), "+f"(c[2]), "+f"(c[3])
                 : "r"(a[0]), "r"(a[1]), "r"(a[2]), "r"(a[3]), "r"(b0), "r"(b1));
}

// ---------------- CSR build -------------------------------------------------
__global__ void k_count(const int* __restrict__ dst) {
    int e = blockIdx.x * blockDim.x + threadIdx.x;
    if (e < EE) atomicAdd(&g_deg[dst[e]], 1);
}
__global__ void k_scan1() {
    int t = threadIdx.x, i = blockIdx.x * 1024 + t;
    int lane = t & 31, wid = t >> 5;
    int orig = (i < NN) ? g_deg[i] : 0;
    int v = orig;
#pragma unroll
    for (int o = 1; o < 32; o <<= 1) {
        int nv = __shfl_up_sync(0xffffffffu, v, o);
        if (lane >= o) v += nv;
    }
    __shared__ int ws[32];
    if (lane == 31) ws[wid] = v;
    __syncthreads();
    if (wid == 0) {
        int wv = ws[lane];
#pragma unroll
        for (int o = 1; o < 32; o <<= 1) {
            int nv = __shfl_up_sync(0xffffffffu, wv, o);
            if (lane >= o) wv += nv;
        }
        ws[lane] = wv;
    }
    __syncthreads();
    int wpre = wid ? ws[wid - 1] : 0;
    if (i < NN) g_rowptr[i] = wpre + v - orig;
    if (t == 0) g_bsum[blockIdx.x] = ws[31];
}
__global__ void k_scan2() {
    __shared__ int s[128];
    int t = threadIdx.x;
    s[t] = (t < NBLK) ? g_bsum[t] : 0;
    __syncthreads();
    for (int o = 1; o < 128; o <<= 1) {
        int add = (t >= o) ? s[t - o] : 0;
        __syncthreads();
        s[t] += add;
        __syncthreads();
    }
    if (t < NBLK) g_bpre[t] = (t == 0) ? 0 : s[t - 1];
}
__global__ void k_scan3() {
    int i = blockIdx.x * 1024 + threadIdx.x;
    if (i < NN) {
        int v = g_rowptr[i] + g_bpre[blockIdx.x];
        g_rowptr[i] = v;
        g_cursor[i] = v;
    }
}
__global__ void k_build(const int* __restrict__ src, const int* __restrict__ dst,
                        const int* __restrict__ et) {
    int e = blockIdx.x * blockDim.x + threadIdx.x;
    if (e < EE) {
        int d = dst[e];
        int p = atomicAdd(&g_cursor[d], 1);
        g_epack[p] = src[e] | (et[e] << 24);
    }
}

// ---------------- W precompute: transpose + bf16 hi/lo split ----------------
__global__ void k_prepw(const float* __restrict__ root, const float* __restrict__ W,
                        __nv_bfloat16* __restrict__ oh, __nv_bfloat16* __restrict__ ol,
                        int dout) {
    int i = blockIdx.x * 256 + threadIdx.x;
    if (i >= dout * KTOT) return;
    int n = i / KTOT, k = i % KTOT;
    float v = (k < 64) ? root[k * dout + n] : W[(size_t)(k - 64) * dout + n];
    __nv_bfloat16 h = __float2bfloat16(v);
    float lo = v - __bfloat162float(h);
    oh[i] = h;
    ol[i] = __float2bfloat16(lo);
}

// ---------------- aggregation -----------------------------------------------
__global__ __launch_bounds__(256) void k_aggregate(const float* __restrict__ feat) {
    __shared__ float S[8][KAGG];
    int wid = threadIdx.x >> 5, lane = threadIdx.x & 31;
    int n = blockIdx.x * 8 + wid;
    if (n >= NN) return;
    float2* Sw = reinterpret_cast<float2*>(S[wid]);
#pragma unroll
    for (int r = 0; r < 8; r++) Sw[r * 32 + lane] = make_float2(0.f, 0.f);
    int start = g_rowptr[n];
    int d = g_deg[n];
    int cnt = 0;
    const float2* fx = reinterpret_cast<const float2*>(feat);
    int pe = (d > 0) ? __ldg(g_epack + start) : 0;
    for (int i = 0; i < d; i++) {
        int cur = pe;
        if (i + 1 < d) pe = __ldg(g_epack + start + i + 1);
        int s = cur & 0xFFFFFF;
        int r = cur >> 24;
        if (lane == r) cnt++;
        float2 v = fx[(size_t)s * 32 + lane];
        float2 t = Sw[r * 32 + lane];
        t.x += v.x; t.y += v.y;
        Sw[r * 32 + lane] = t;
    }
    float inv = 1.0f / (float)max(cnt, 1);
    float2* Ao = reinterpret_cast<float2*>(g_Agg + (size_t)n * KAGG);
#pragma unroll
    for (int r = 0; r < 8; r++) {
        float fr = __shfl_sync(0xffffffffu, inv, r);
        float2 sv = Sw[r * 32 + lane];
        Ao[r * 32 + lane] = make_float2(sv.x * fr, sv.y * fr);
    }
}

// ---------------- mma.sync bf16 3-pass GEMM ---------------------------------
// out = act(bias + [X | Agg] @ Wt^T), virtual K = 576, chunks of 64.
// A split to bf16 hi/lo in-kernel; B hi/lo precomputed (n-major).
template <int DOUT, bool RELU>
__global__ __launch_bounds__(256, 2) void k_gemm_mma(
    const float* __restrict__ X, const float* __restrict__ Agg,
    const __nv_bfloat16* __restrict__ Wth, const __nv_bfloat16* __restrict__ Wtl,
    const float* __restrict__ bias, float* __restrict__ out) {
    constexpr int NT = DOUT / 8;        // n-tiles per warp
    constexpr int BP = 256 / DOUT;      // B copy: parts per row
    constexpr int BV = (KC * 2 / BP) / 16;  // uint4 per thread per B buffer

    __shared__ __align__(16) __nv_bfloat16 Ah[128 * AS];
    __shared__ __align__(16) __nv_bfloat16 Al[128 * AS];
    __shared__ __align__(16) __nv_bfloat16 Bh[DOUT * AS];
    __shared__ __align__(16) __nv_bfloat16 Bl[DOUT * AS];

    uint32_t sAh = smem_u32(Ah), sAl = smem_u32(Al);
    uint32_t sBh = smem_u32(Bh), sBl = smem_u32(Bl);

    int tid = threadIdx.x;
    int w = tid >> 5, l = tid & 31;
    int m0 = blockIdx.x * 128;

    // A load mapping: row = tid/2, half = tid&1 (32 floats each)
    int arow = tid >> 1, aseg = tid & 1;
    int mg = m0 + arow;
    bool aval = (mg < NN);
    // B copy mapping
    int bn = tid % DOUT, bpart = tid / DOUT;

    float4 a4[8];
    uint4 bh4[BV], bl4[BV];

    auto loadA = [&](int c) {
        const float* Asrc = c ? Agg : X;
        int lda = c ? KAGG : 64;
        int koff = c ? (c - 1) * KC : 0;
        if (aval) {
            const float4* ap = reinterpret_cast<const float4*>(Asrc + (size_t)mg * lda + koff) + aseg * 8;
#pragma unroll
            for (int j = 0; j < 8; j++) a4[j] = ap[j];
        } else {
#pragma unroll
            for (int j = 0; j < 8; j++) a4[j] = make_float4(0.f, 0.f, 0.f, 0.f);
        }
    };
    auto loadB = [&](int c) {
        size_t off = (size_t)bn * KTOT + c * KC;  // bf16 units
        const uint4* bh = reinterpret_cast<const uint4*>(Wth + off) + bpart * BV;
        const uint4* bl = reinterpret_cast<const uint4*>(Wtl + off) + bpart * BV;
#pragma unroll
        for (int v = 0; v < BV; v++) { bh4[v] = bh[v]; bl4[v] = bl[v]; }
    };
    auto storeT = [&]() {
        uint32_t abase = (uint32_t)(arow * (AS * 2) + aseg * 64);
#pragma unroll
        for (int jj = 0; jj < 4; jj++) {
            float4 p0 = a4[2 * jj], p1 = a4[2 * jj + 1];
            uint32_t h0 = cvt2(p0.x, p0.y), h1 = cvt2(p0.z, p0.w);
            uint32_t h2 = cvt2(p1.x, p1.y), h3 = cvt2(p1.z, p1.w);
            float r0 = p0.x - __uint_as_float(h0 << 16);
            float r1 = p0.y - __uint_as_float(h0 & 0xFFFF0000u);
            float r2 = p0.z - __uint_as_float(h1 << 16);
            float r3 = p0.w - __uint_as_float(h1 & 0xFFFF0000u);
            float r4 = p1.x - __uint_as_float(h2 << 16);
            float r5 = p1.y - __uint_as_float(h2 & 0xFFFF0000u);
            float r6 = p1.z - __uint_as_float(h3 << 16);
            float r7 = p1.w - __uint_as_float(h3 & 0xFFFF0000u);
            uint32_t l0 = cvt2(r0, r1), l1 = cvt2(r2, r3);
            uint32_t l2 = cvt2(r4, r5), l3 = cvt2(r6, r7);
            sts128(sAh + abase + jj * 16, h0, h1, h2, h3);
            sts128(sAl + abase + jj * 16, l0, l1, l2, l3);
        }
        uint32_t bbase = (uint32_t)(bn * (AS * 2) + bpart * (BV * 16));
#pragma unroll
        for (int v = 0; v < BV; v++) {
            sts128(sBh + bbase + v * 16, bh4[v].x, bh4[v].y, bh4[v].z, bh4[v].w);
            sts128(sBl + bbase + v * 16, bl4[v].x, bl4[v].y, bl4[v].z, bl4[v].w);
        }
    };

    float acc[NT][4];
#pragma unroll
    for (int t = 0; t < NT; t++)
#pragma unroll
        for (int q = 0; q < 4; q++) acc[t][q] = 0.f;

    // ldmatrix lane address (within warp): row offset + k offset
    int lrow = w * 16 + (l & 7) + ((l >> 3) & 1) * 8;
    int lkb = ((l >> 4) & 1) * 16;  // bytes
    uint32_t aoff = (uint32_t)(lrow * (AS * 2)) + lkb;
    // B frag address components
    int bfn = l >> 2;           // n within tile
    int bfk = (l & 3) * 4;      // k*2 bytes

    loadA(0);
    loadB(0);
    for (int c = 0; c < NCH; c++) {
        storeT();
        __syncthreads();
        if (c + 1 < NCH) { loadA(c + 1); loadB(c + 1); }
#pragma unroll
        for (int ks = 0; ks < 4; ks++) {
            uint32_t fah[4], fal[4];
            ldmx4(fah, sAh + aoff + ks * 32);
            ldmx4(fal, sAl + aoff + ks * 32);
#pragma unroll
            for (int t = 0; t < NT; t++) {
                uint32_t ba = (uint32_t)((t * 8 + bfn) * (AS * 2)) + ks * 32 + bfk;
                uint32_t bh0 = lds32(sBh + ba), bh1 = lds32(sBh + ba + 16);
                uint32_t bl0 = lds32(sBl + ba), bl1 = lds32(sBl + ba + 16);
                mma16816(acc[t], fah, bh0, bh1);
                mma16816(acc[t], fah, bl0, bl1);
                mma16816(acc[t], fal, bh0, bh1);
            }
        }
        __syncthreads();
    }

    // epilogue: lane l, tile t -> rows m0+w*16+l/4 (+8), cols t*8+(l%4)*2
    int r0 = m0 + w * 16 + (l >> 2);
    int cb = (l & 3) * 2;
#pragma unroll
    for (int t = 0; t < NT; t++) {
        int n = t * 8 + cb;
        float b0 = __ldg(bias + n), b1 = __ldg(bias + n + 1);
        if (r0 < NN) {
            float v0 = acc[t][0] + b0, v1 = acc[t][1] + b1;
            if (RELU) { v0 = fmaxf(v0, 0.f); v1 = fmaxf(v1, 0.f); }
            *reinterpret_cast<float2*>(out + (size_t)r0 * DOUT + n) = make_float2(v0, v1);
        }
        if (r0 + 8 < NN) {
            float v2 = acc[t][2] + b0, v3 = acc[t][3] + b1;
            if (RELU) { v2 = fmaxf(v2, 0.f); v3 = fmaxf(v3, 0.f); }
            *reinterpret_cast<float2*>(out + (size_t)(r0 + 8) * DOUT + n) = make_float2(v2, v3);
        }
    }
}

// ---------------- launch ----------------------------------------------------
extern "C" void kernel_launch(void* const* d_in, const int* in_sizes, int n_in,
                              void* d_out, int out_size) {
    const float* x     = (const float*)d_in[0];
    const float* W1    = (const float*)d_in[1];
    const float* root1 = (const float*)d_in[2];
    const float* b1    = (const float*)d_in[3];
    const float* W2    = (const float*)d_in[4];
    const float* root2 = (const float*)d_in[5];
    const float* b2    = (const float*)d_in[6];
    const int*   src   = (const int*)d_in[7];
    const int*   dst   = (const int*)d_in[8];
    const int*   et    = (const int*)d_in[9];
    float* out = (float*)d_out;

    float *H, *Agg;
    int* degp;
    __nv_bfloat16 *w1h, *w1l, *w2h, *w2l;
    cudaGetSymbolAddress((void**)&H, g_H);
    cudaGetSymbolAddress((void**)&Agg, g_Agg);
    cudaGetSymbolAddress((void**)&degp, g_deg);
    cudaGetSymbolAddress((void**)&w1h, g_Wt1h);
    cudaGetSymbolAddress((void**)&w1l, g_Wt1l);
    cudaGetSymbolAddress((void**)&w2h, g_Wt2h);
    cudaGetSymbolAddress((void**)&w2l, g_Wt2l);

    const int egrid = (EE + 255) / 256;
    const int ngrid = NBLK;
    const int agrid = (NN + 7) / 8;
    const int ggrid = (NN + 127) / 128;

    // CSR build
    cudaMemsetAsync(degp, 0, NN * sizeof(int));
    k_count<<<egrid, 256>>>(dst);
    k_scan1<<<ngrid, 1024>>>();
    k_scan2<<<1, 128>>>();
    k_scan3<<<ngrid, 1024>>>();
    k_build<<<egrid, 256>>>(src, dst, et);

    // weight prep
    k_prepw<<<(64 * KTOT + 255) / 256, 256>>>(root1, W1, w1h, w1l, 64);
    k_prepw<<<(32 * KTOT + 255) / 256, 256>>>(root2, W2, w2h, w2l, 32);

    // Layer 1
    k_aggregate<<<agrid, 256>>>(x);
    k_gemm_mma<64, true><<<ggrid, 256>>>(x, Agg, w1h, w1l, b1, H);

    // Layer 2
    k_aggregate<<<agrid, 256>>>(H);
    k_gemm_mma<32, false><<<ggrid, 256>>>(H, Agg, w2h, w2l, b2, out);
}

// round 5
// speedup vs baseline: 2.1980x; 1.1230x over previous
#include <cuda_runtime.h>
#include <cuda_bf16.h>
#include <cstdint>

typedef unsigned long long ull;

// Problem constants
constexpr int NN = 100000;
constexpr int EE = 1250000;
constexpr int KTOT = 576;                 // 64 (root) + 8*64
constexpr int NK = NN * 8;                // (node, rel) keys
constexpr int NBLK2 = (NK + 1023) / 1024; // 782 scan blocks
constexpr int KC = 64;                    // k per chunk
constexpr int NCH = KTOT / KC;            // 9
constexpr int AS = 72;                    // smem row stride in bf16 (144 B)

// ---------------- scratch ---------------------------------------------------
__device__ int g_cnt[NK];      // per (node,rel) edge count (kept for normalize)
__device__ int g_rowptr[NK];
__device__ int g_cursor[NK];
__device__ int g_epack[EE];    // src node ids, sorted by (dst, rel)
__device__ int g_bsum[NBLK2];
__device__ int g_bpre[NBLK2];
__device__ float g_H[(size_t)NN * 64];
__device__ __nv_bfloat16 g_Wt1h[64 * KTOT];
__device__ __nv_bfloat16 g_Wt1l[64 * KTOT];
__device__ __nv_bfloat16 g_Wt2h[32 * KTOT];
__device__ __nv_bfloat16 g_Wt2l[32 * KTOT];

// ---------------- helpers ---------------------------------------------------
__device__ __forceinline__ uint32_t smem_u32(const void* p) {
    uint32_t a;
    asm("{ .reg .u64 t; cvta.to.shared.u64 t, %1; cvt.u32.u64 %0, t; }" : "=r"(a) : "l"(p));
    return a;
}
__device__ __forceinline__ void sts128(uint32_t a, uint32_t x, uint32_t y, uint32_t z, uint32_t w) {
    asm volatile("st.shared.v4.b32 [%0], {%1,%2,%3,%4};" :: "r"(a), "r"(x), "r"(y), "r"(z), "r"(w) : "memory");
}
__device__ __forceinline__ uint32_t lds32(uint32_t a) {
    uint32_t v;
    asm volatile("ld.shared.b32 %0, [%1];" : "=r"(v) : "r"(a));
    return v;
}
__device__ __forceinline__ uint32_t cvt2(float lo, float hi) {
    uint32_t r;
    asm("cvt.rn.satfinite.bf16x2.f32 %0, %1, %2;" : "=r"(r) : "f"(hi), "f"(lo));
    return r;
}
__device__ __forceinline__ void ldmx4(uint32_t* r, uint32_t a) {
    asm volatile("ldmatrix.sync.aligned.m8n8.x4.shared.b16 {%0,%1,%2,%3}, [%4];"
                 : "=r"(r[0]), "=r"(r[1]), "=r"(r[2]), "=r"(r[3]) : "r"(a));
}
__device__ __forceinline__ void mma16816(float* c, const uint32_t* a, uint32_t b0, uint32_t b1) {
    asm volatile("mma.sync.aligned.m16n8k16.row.col.f32.bf16.bf16.f32 "
                 "{%0,%1,%2,%3}, {%4,%5,%6,%7}, {%8,%9}, {%0,%1,%2,%3};"
                 : "+f"(c[0]), "+f"(c[1]), "+f"(c[2]), "+f"(c[3])
                 : "r"(a[0]), "r"(a[1]), "r"(a[2]), "r"(a[3]), "r"(b0), "r"(b1));
}

// ---------------- CSR build over keys (dst*8 + rel) --------------------------
__global__ void k_count(const int* __restrict__ dst, const int* __restrict__ et) {
    int e = blockIdx.x * blockDim.x + threadIdx.x;
    if (e < EE) atomicAdd(&g_cnt[dst[e] * 8 + et[e]], 1);
}
__global__ void k_scan1() {
    int t = threadIdx.x, i = blockIdx.x * 1024 + t;
    int lane = t & 31, wid = t >> 5;
    int orig = (i < NK) ? g_cnt[i] : 0;
    int v = orig;
#pragma unroll
    for (int o = 1; o < 32; o <<= 1) {
        int nv = __shfl_up_sync(0xffffffffu, v, o);
        if (lane >= o) v += nv;
    }
    __shared__ int ws[32];
    if (lane == 31) ws[wid] = v;
    __syncthreads();
    if (wid == 0) {
        int wv = ws[lane];
#pragma unroll
        for (int o = 1; o < 32; o <<= 1) {
            int nv = __shfl_up_sync(0xffffffffu, wv, o);
            if (lane >= o) wv += nv;
        }
        ws[lane] = wv;
    }
    __syncthreads();
    int wpre = wid ? ws[wid - 1] : 0;
    if (i < NK) g_rowptr[i] = wpre + v - orig;
    if (t == 0) g_bsum[blockIdx.x] = ws[31];
}
__global__ void k_scan2() {  // 1 block, 1024 threads, NBLK2 <= 1024
    int t = threadIdx.x;
    int lane = t & 31, wid = t >> 5;
    int orig = (t < NBLK2) ? g_bsum[t] : 0;
    int v = orig;
#pragma unroll
    for (int o = 1; o < 32; o <<= 1) {
        int nv = __shfl_up_sync(0xffffffffu, v, o);
        if (lane >= o) v += nv;
    }
    __shared__ int ws[32];
    if (lane == 31) ws[wid] = v;
    __syncthreads();
    if (wid == 0) {
        int wv = ws[lane];
#pragma unroll
        for (int o = 1; o < 32; o <<= 1) {
            int nv = __shfl_up_sync(0xffffffffu, wv, o);
            if (lane >= o) wv += nv;
        }
        ws[lane] = wv;
    }
    __syncthreads();
    int wpre = wid ? ws[wid - 1] : 0;
    if (t < NBLK2) g_bpre[t] = wpre + v - orig;
}
__global__ void k_scan3() {
    int i = blockIdx.x * 1024 + threadIdx.x;
    if (i < NK) {
        int v = g_rowptr[i] + g_bpre[blockIdx.x];
        g_rowptr[i] = v;
        g_cursor[i] = v;
    }
}
__global__ void k_build(const int* __restrict__ src, const int* __restrict__ dst,
                        const int* __restrict__ et) {
    int e = blockIdx.x * blockDim.x + threadIdx.x;
    if (e < EE) {
        int p = atomicAdd(&g_cursor[dst[e] * 8 + et[e]], 1);
        g_epack[p] = src[e];
    }
}

// ---------------- W precompute: transpose + bf16 hi/lo split ----------------
__global__ void k_prepw(const float* __restrict__ root, const float* __restrict__ W,
                        __nv_bfloat16* __restrict__ oh, __nv_bfloat16* __restrict__ ol,
                        int dout) {
    int i = blockIdx.x * 256 + threadIdx.x;
    if (i >= dout * KTOT) return;
    int n = i / KTOT, k = i % KTOT;
    float v = (k < 64) ? root[k * dout + n] : W[(size_t)(k - 64) * dout + n];
    __nv_bfloat16 h = __float2bfloat16(v);
    float lo = v - __bfloat162float(h);
    oh[i] = h;
    ol[i] = __float2bfloat16(lo);
}

// ---------------- fused aggregate + mma.sync bf16 3-pass GEMM ---------------
// out = act(bias + X@root + sum_r mean_agg_r(X)@W_r)
// Chunk 0: direct X row. Chunk c>=1 (relation r=c-1): gather-and-average
// x[src] over this node's relation-r edges (CSR sorted by (dst, rel)).
template <int DOUT, bool RELU>
__global__ __launch_bounds__(256, 2) void k_gemm_fused(
    const float* __restrict__ X,
    const __nv_bfloat16* __restrict__ Wth, const __nv_bfloat16* __restrict__ Wtl,
    const float* __restrict__ bias, float* __restrict__ out) {
    constexpr int NT = DOUT / 8;            // n-tiles per warp
    constexpr int BP = 256 / DOUT;          // B copy: parts per row
    constexpr int BV = (KC * 2 / BP) / 16;  // uint4 per thread per B buffer

    __shared__ __align__(16) __nv_bfloat16 Ah[128 * AS];
    __shared__ __align__(16) __nv_bfloat16 Al[128 * AS];
    __shared__ __align__(16) __nv_bfloat16 Bh[DOUT * AS];
    __shared__ __align__(16) __nv_bfloat16 Bl[DOUT * AS];

    uint32_t sAh = smem_u32(Ah), sAl = smem_u32(Al);
    uint32_t sBh = smem_u32(Bh), sBl = smem_u32(Bl);

    int tid = threadIdx.x;
    int w = tid >> 5, l = tid & 31;
    int m0 = blockIdx.x * 128;

    // A mapping: row = tid/2, half = tid&1 (32 floats each)
    int arow = tid >> 1, aseg = tid & 1;
    int mg = m0 + arow;
    bool aval = (mg < NN);
    // B copy mapping
    int bn = tid % DOUT, bpart = tid / DOUT;

    float4 a4[8];
    uint4 bh4[BV], bl4[BV];

    auto loadA = [&](int c) {
        if (!aval) {
#pragma unroll
            for (int j = 0; j < 8; j++) a4[j] = make_float4(0.f, 0.f, 0.f, 0.f);
            return;
        }
        if (c == 0) {
            const float4* ap = reinterpret_cast<const float4*>(X + (size_t)mg * 64) + aseg * 8;
#pragma unroll
            for (int j = 0; j < 8; j++) a4[j] = ap[j];
        } else {
            int key = mg * 8 + (c - 1);
            int st = __ldg(g_rowptr + key);
            int cn = __ldg(g_cnt + key);
#pragma unroll
            for (int j = 0; j < 8; j++) a4[j] = make_float4(0.f, 0.f, 0.f, 0.f);
            for (int i = 0; i < cn; i++) {
                int s = __ldg(g_epack + st + i);
                const float4* fp = reinterpret_cast<const float4*>(X + (size_t)s * 64) + aseg * 8;
#pragma unroll
                for (int j = 0; j < 8; j++) {
                    float4 v = fp[j];
                    a4[j].x += v.x; a4[j].y += v.y; a4[j].z += v.z; a4[j].w += v.w;
                }
            }
            float inv = 1.0f / (float)max(cn, 1);
#pragma unroll
            for (int j = 0; j < 8; j++) {
                a4[j].x *= inv; a4[j].y *= inv; a4[j].z *= inv; a4[j].w *= inv;
            }
        }
    };
    auto loadB = [&](int c) {
        size_t off = (size_t)bn * KTOT + c * KC;  // bf16 units
        const uint4* bh = reinterpret_cast<const uint4*>(Wth + off) + bpart * BV;
        const uint4* bl = reinterpret_cast<const uint4*>(Wtl + off) + bpart * BV;
#pragma unroll
        for (int v = 0; v < BV; v++) { bh4[v] = bh[v]; bl4[v] = bl[v]; }
    };
    auto storeT = [&]() {
        uint32_t abase = (uint32_t)(arow * (AS * 2) + aseg * 64);
#pragma unroll
        for (int jj = 0; jj < 4; jj++) {
            float4 p0 = a4[2 * jj], p1 = a4[2 * jj + 1];
            uint32_t h0 = cvt2(p0.x, p0.y), h1 = cvt2(p0.z, p0.w);
            uint32_t h2 = cvt2(p1.x, p1.y), h3 = cvt2(p1.z, p1.w);
            float r0 = p0.x - __uint_as_float(h0 << 16);
            float r1 = p0.y - __uint_as_float(h0 & 0xFFFF0000u);
            float r2 = p0.z - __uint_as_float(h1 << 16);
            float r3 = p0.w - __uint_as_float(h1 & 0xFFFF0000u);
            float r4 = p1.x - __uint_as_float(h2 << 16);
            float r5 = p1.y - __uint_as_float(h2 & 0xFFFF0000u);
            float r6 = p1.z - __uint_as_float(h3 << 16);
            float r7 = p1.w - __uint_as_float(h3 & 0xFFFF0000u);
            uint32_t l0 = cvt2(r0, r1), l1 = cvt2(r2, r3);
            uint32_t l2 = cvt2(r4, r5), l3 = cvt2(r6, r7);
            sts128(sAh + abase + jj * 16, h0, h1, h2, h3);
            sts128(sAl + abase + jj * 16, l0, l1, l2, l3);
        }
        uint32_t bbase = (uint32_t)(bn * (AS * 2) + bpart * (BV * 16));
#pragma unroll
        for (int v = 0; v < BV; v++) {
            sts128(sBh + bbase + v * 16, bh4[v].x, bh4[v].y, bh4[v].z, bh4[v].w);
            sts128(sBl + bbase + v * 16, bl4[v].x, bl4[v].y, bl4[v].z, bl4[v].w);
        }
    };

    float acc[NT][4];
#pragma unroll
    for (int t = 0; t < NT; t++)
#pragma unroll
        for (int q = 0; q < 4; q++) acc[t][q] = 0.f;

    // ldmatrix lane address
    int lrow = w * 16 + (l & 7) + ((l >> 3) & 1) * 8;
    int lkb = ((l >> 4) & 1) * 16;  // bytes
    uint32_t aoff = (uint32_t)(lrow * (AS * 2)) + lkb;
    // B frag address components
    int bfn = l >> 2;
    int bfk = (l & 3) * 4;

    loadA(0);
    loadB(0);
    for (int c = 0; c < NCH; c++) {
        storeT();
        __syncthreads();
        if (c + 1 < NCH) { loadA(c + 1); loadB(c + 1); }
#pragma unroll
        for (int ks = 0; ks < 4; ks++) {
            uint32_t fah[4], fal[4];
            ldmx4(fah, sAh + aoff + ks * 32);
            ldmx4(fal, sAl + aoff + ks * 32);
#pragma unroll
            for (int t = 0; t < NT; t++) {
                uint32_t ba = (uint32_t)((t * 8 + bfn) * (AS * 2)) + ks * 32 + bfk;
                uint32_t bh0 = lds32(sBh + ba), bh1 = lds32(sBh + ba + 16);
                uint32_t bl0 = lds32(sBl + ba), bl1 = lds32(sBl + ba + 16);
                mma16816(acc[t], fah, bh0, bh1);
                mma16816(acc[t], fah, bl0, bl1);
                mma16816(acc[t], fal, bh0, bh1);
            }
        }
        __syncthreads();
    }

    // epilogue
    int r0 = m0 + w * 16 + (l >> 2);
    int cb = (l & 3) * 2;
#pragma unroll
    for (int t = 0; t < NT; t++) {
        int n = t * 8 + cb;
        float b0 = __ldg(bias + n), b1 = __ldg(bias + n + 1);
        if (r0 < NN) {
            float v0 = acc[t][0] + b0, v1 = acc[t][1] + b1;
            if (RELU) { v0 = fmaxf(v0, 0.f); v1 = fmaxf(v1, 0.f); }
            *reinterpret_cast<float2*>(out + (size_t)r0 * DOUT + n) = make_float2(v0, v1);
        }
        if (r0 + 8 < NN) {
            float v2 = acc[t][2] + b0, v3 = acc[t][3] + b1;
            if (RELU) { v2 = fmaxf(v2, 0.f); v3 = fmaxf(v3, 0.f); }
            *reinterpret_cast<float2*>(out + (size_t)(r0 + 8) * DOUT + n) = make_float2(v2, v3);
        }
    }
}

// ---------------- launch ----------------------------------------------------
extern "C" void kernel_launch(void* const* d_in, const int* in_sizes, int n_in,
                              void* d_out, int out_size) {
    const float* x     = (const float*)d_in[0];
    const float* W1    = (const float*)d_in[1];
    const float* root1 = (const float*)d_in[2];
    const float* b1    = (const float*)d_in[3];
    const float* W2    = (const float*)d_in[4];
    const float* root2 = (const float*)d_in[5];
    const float* b2    = (const float*)d_in[6];
    const int*   src   = (const int*)d_in[7];
    const int*   dst   = (const int*)d_in[8];
    const int*   et    = (const int*)d_in[9];
    float* out = (float*)d_out;

    float* H;
    int* cntp;
    __nv_bfloat16 *w1h, *w1l, *w2h, *w2l;
    cudaGetSymbolAddress((void**)&H, g_H);
    cudaGetSymbolAddress((void**)&cntp, g_cnt);
    cudaGetSymbolAddress((void**)&w1h, g_Wt1h);
    cudaGetSymbolAddress((void**)&w1l, g_Wt1l);
    cudaGetSymbolAddress((void**)&w2h, g_Wt2h);
    cudaGetSymbolAddress((void**)&w2l, g_Wt2l);

    const int egrid = (EE + 255) / 256;
    const int ggrid = (NN + 127) / 128;

    // CSR build over (dst, rel) keys
    cudaMemsetAsync(cntp, 0, NK * sizeof(int));
    k_count<<<egrid, 256>>>(dst, et);
    k_scan1<<<NBLK2, 1024>>>();
    k_scan2<<<1, 1024>>>();
    k_scan3<<<NBLK2, 1024>>>();
    k_build<<<egrid, 256>>>(src, dst, et);

    // weight prep
    k_prepw<<<(64 * KTOT + 255) / 256, 256>>>(root1, W1, w1h, w1l, 64);
    k_prepw<<<(32 * KTOT + 255) / 256, 256>>>(root2, W2, w2h, w2l, 32);

    // Layer 1 (fused aggregate+GEMM)
    k_gemm_fused<64, true><<<ggrid, 256>>>(x, w1h, w1l, b1, H);

    // Layer 2
    k_gemm_fused<32, false><<<ggrid, 256>>>(H, w2h, w2l, b2, out);
}